// round 17
// baseline (speedup 1.0000x reference)
#include <cuda_runtime.h>
#include <cstdint>

// Problem constants
#define B_ROWS   65536
#define N_SPARSE 26
#define VOCAB    5000
#define N_DENSE  13

#define THREADS    1024
#define ROWS_PB    448        // direct half: 1 thread/row; cached half: 1 thread/row
#define NBLOCKS    147        // 146*448=65408, last block 128 rows
#define CHUNK_ROWS 112
#define N_CHUNKS   4

#define N_CACHED 18           // features [0,18) via smem; [18,26) + crosses direct
#define PASS_NF  3
#define N_PASSES 6

// Dynamic smem layout (bytes), 16B-aligned
#define BUF_BYTES   (PASS_NF * VOCAB * 4)       // 60000
#define BUF_VEC     (BUF_BYTES / 16)            // 3750 float4 per slice
#define IDX_OFF     (2 * BUF_BYTES)             // 120000
#define IDX_BYTES   (ROWS_PB * N_SPARSE * 4)    // 46592
#define PARTD_OFF   (IDX_OFF + IDX_BYTES)       // 166592
#define PARTC_OFF   (PARTD_OFF + ROWS_PB * 4)   // 168384
#define MBAR_OFF    (PARTC_OFF + ROWS_PB * 4)   // 170176
#define SMEM_TOTAL  (MBAR_OFF + 4 * 8)          // 170208

__device__ __forceinline__ uint32_t smem_u32(const void* p) {
    return (uint32_t)__cvta_generic_to_shared(p);
}
__device__ __forceinline__ void mbar_init(uint32_t mbar, uint32_t count) {
    asm volatile("mbarrier.init.shared.b64 [%0], %1;" :: "r"(mbar), "r"(count) : "memory");
}
__device__ __forceinline__ void mbar_expect_tx(uint32_t mbar, uint32_t bytes) {
    asm volatile("mbarrier.arrive.expect_tx.shared.b64 _, [%0], %1;"
                 :: "r"(mbar), "r"(bytes) : "memory");
}
__device__ __forceinline__ void mbar_wait(uint32_t mbar, uint32_t parity) {
    uint32_t done = 0;
    while (!done) {
        asm volatile(
            "{\n\t.reg .pred p;\n\t"
            "mbarrier.try_wait.parity.acquire.cta.shared::cta.b64 p, [%1], %2, 0x989680;\n\t"
            "selp.b32 %0, 1, 0, p;\n\t}"
            : "=r"(done) : "r"(mbar), "r"(parity) : "memory");
    }
}
__device__ __forceinline__ void bulk_g2s(uint32_t dst, const void* src,
                                         uint32_t bytes, uint32_t mbar) {
    asm volatile(
        "cp.async.bulk.shared::cta.global.mbarrier::complete_tx::bytes [%0], [%1], %2, [%3];"
        :: "r"(dst), "l"(src), "r"(bytes), "r"(mbar) : "memory");
}

__global__ __launch_bounds__(THREADS, 1) void wide_kernel(
    const float* __restrict__ dense,        // [B, 13]
    const float* __restrict__ emb_table,    // [26, 5000]
    const float* __restrict__ cross_table0, // [25e6]
    const float* __restrict__ cross_table1, // [25e6]
    const float* __restrict__ dense_w,      // [13]
    const int*   __restrict__ sparse_idx,   // [B, 26] int32
    float*       __restrict__ out)          // [B]
{
    extern __shared__ __align__(16) char smem[];
    int*   s_idx    = (int*)(smem + IDX_OFF);
    float* s_part_d = (float*)(smem + PARTD_OFF);
    float* s_part_c = (float*)(smem + PARTC_OFF);

    const uint32_t mb_io0 = smem_u32(smem + MBAR_OFF);   // 4 io chunk barriers

    const int tid  = threadIdx.x;
    const int row0 = blockIdx.x * ROWS_PB;
    const int rows = min(ROWS_PB, B_ROWS - row0);

    if (tid == 0) {
        #pragma unroll
        for (int c = 0; c < N_CHUNKS; c++) mbar_init(mb_io0 + 8 * c, 1);
    }
    __syncthreads();

    // idx staging via chunked TMA (only TMA user -> queue is empty otherwise).
    if (tid == 0) {
        #pragma unroll
        for (int c = 0; c < N_CHUNKS; c++) {
            const int crow0 = c * CHUNK_ROWS;
            const int crows = max(0, min(CHUNK_ROWS, rows - crow0));
            const uint32_t ib = (uint32_t)crows * N_SPARSE * 4;
            mbar_expect_tx(mb_io0 + 8 * c, ib);   // 0 bytes -> flips immediately
            if (crows > 0) {
                bulk_g2s(smem_u32(s_idx + crow0 * N_SPARSE),
                         sparse_idx + (size_t)(row0 + crow0) * N_SPARSE, ib, mb_io0 + 8 * c);
            }
        }
    }

    if (tid < 512) {
        // ---------------- DIRECT HALF: 1 thread per row ----------------
        const int r = tid;
        if (r < rows) {
            mbar_wait(mb_io0 + 8 * min(r / CHUNK_ROWS, N_CHUNKS - 1), 0);

            const int* my = &s_idx[r * N_SPARSE];
            float a = 0.0f;
            // 2 DRAM cross gathers first (longest latency), then 8 L2-hot embs,
            // then dense row (contiguous gmem) — 23 independent loads in flight.
            a += __ldg(&cross_table0[my[0] * VOCAB + my[1]]);
            a += __ldg(&cross_table1[my[2] * VOCAB + my[3]]);
            #pragma unroll
            for (int f = N_CACHED; f < N_SPARSE; f++)
                a += __ldg(&emb_table[f * VOCAB + my[f]]);
            const float* dr = &dense[(size_t)(row0 + r) * N_DENSE];
            #pragma unroll
            for (int d = 0; d < N_DENSE; d++)
                a += __ldg(&dr[d]) * __ldg(&dense_w[d]);

            s_part_d[r] = a;
        }
    } else {
        // ------------- CACHED HALF: copiers + gatherers (same warps) -------------
        const int ctid = tid - 512;          // 0..511
        float4* bufA = (float4*)smem;
        float4* bufB = (float4*)(smem + BUF_BYTES);

        // Prime both buffers with slices 0 and 1 (LDG->STS, 8 float4/thread each).
        {
            const float4* s0 = (const float4*)(emb_table + 0 * PASS_NF * VOCAB);
            const float4* s1 = (const float4*)(emb_table + 1 * PASS_NF * VOCAB);
            #pragma unroll 2
            for (int j = ctid; j < BUF_VEC; j += 512) {
                bufA[j] = __ldg(&s0[j]);
                bufB[j] = __ldg(&s1[j]);
            }
        }

        const int r = ctid;
        if (r < rows) {
            mbar_wait(mb_io0 + 8 * min(r / CHUNK_ROWS, N_CHUNKS - 1), 0);
        }
        // Barrier over cached half only: copies visible (bar.sync drains STS).
        asm volatile("bar.sync 1, 512;" ::: "memory");

        const int* my = &s_idx[r * N_SPARSE];   // read only when r < rows
        float a = 0.0f;

        #pragma unroll
        for (int p = 0; p < N_PASSES; p++) {
            const float* tb = (const float*)(smem + (p & 1) * BUF_BYTES);

            if (r < rows) {
                const int f0 = p * PASS_NF;
                a += tb[0 * VOCAB + my[f0 + 0]];
                a += tb[1 * VOCAB + my[f0 + 1]];
                a += tb[2 * VOCAB + my[f0 + 2]];
            }

            // All cached threads done reading buf[p&1].
            asm volatile("bar.sync 1, 512;" ::: "memory");

            // Refill buf[p&1] with slice p+2; visibility guaranteed by the
            // pass p+1 barrier (which drains these STS) before pass p+2 reads.
            if (p + 2 < N_PASSES) {
                float4* dst = (p & 1) ? bufB : bufA;
                const float4* src = (const float4*)(emb_table + (p + 2) * PASS_NF * VOCAB);
                #pragma unroll 2
                for (int j = ctid; j < BUF_VEC; j += 512) {
                    dst[j] = __ldg(&src[j]);
                }
            }
        }
        if (r < rows) s_part_c[r] = a;
    }

    __syncthreads();

    // Combine halves and store.
    if (tid < rows) out[row0 + tid] = s_part_d[tid] + s_part_c[tid];
}

extern "C" void kernel_launch(void* const* d_in, const int* in_sizes, int n_in,
                              void* d_out, int out_size)
{
    const float* dense        = nullptr;
    const float* emb_table    = nullptr;
    const float* cross_table0 = nullptr;
    const float* cross_table1 = nullptr;
    const float* dense_w      = nullptr;
    const int*   sparse_idx   = nullptr;

    for (int i = 0; i < n_in; i++) {
        const long long sz = in_sizes[i];
        if      (sz == (long long)B_ROWS * N_DENSE)   dense      = (const float*)d_in[i];
        else if (sz == (long long)N_SPARSE * VOCAB)   emb_table  = (const float*)d_in[i];
        else if (sz == (long long)VOCAB * VOCAB) {
            if (!cross_table0) cross_table0 = (const float*)d_in[i];
            else               cross_table1 = (const float*)d_in[i];
        }
        else if (sz == N_DENSE)                       dense_w    = (const float*)d_in[i];
        else if (sz == (long long)B_ROWS * N_SPARSE)  sparse_idx = (const int*)d_in[i];
    }

    float* out = (float*)d_out;

    static bool attr_set = false;
    if (!attr_set) {
        cudaFuncSetAttribute(wide_kernel,
                             cudaFuncAttributeMaxDynamicSharedMemorySize, SMEM_TOTAL);
        attr_set = true;
    }

    wide_kernel<<<NBLOCKS, THREADS, SMEM_TOTAL>>>(dense, emb_table,
                                                  cross_table0, cross_table1,
                                                  dense_w, sparse_idx, out);
}